// round 7
// baseline (speedup 1.0000x reference)
#include <cuda_runtime.h>
#include <cuda_bf16.h>
#include <math.h>

// Problem constants (fixed shapes)
#define SEQ   8
#define BB    8
#define CIN   16
#define HH    96
#define WW    96
#define HW    (HH*WW)      // 9216
#define NF    64
#define LL    5
#define C3    (3*NF)       // 192
#define CF    32           // f channels
#define CFL   (2*LL)       // 10 flow channels
#define KW    (LL*NF)      // 320 warped channels

// -------------------- scratch (device globals; no allocation) --------------------
__device__ float g_i2h  [(size_t)SEQ * BB * C3 * HW];
__device__ float g_f    [(size_t)BB * CF  * HW];
__device__ float g_flows[(size_t)BB * CFL * HW];
__device__ float g_warp [(size_t)BB * KW  * HW];
__device__ float g_h2h  [(size_t)BB * C3  * HW];

// fast transcendentals (accuracy budget is 1e-3; these are ~1e-7 level here)
__device__ __forceinline__ float fsigmoid(float x) {
    return 1.f / (1.f + __expf(-x));
}
__device__ __forceinline__ float ftanh(float x) {
    float e = __expf(2.f * x);
    return (e - 1.f) / (e + 1.f);
}

// -------------------- utility --------------------
__global__ void copy_kernel(const float* __restrict__ src, float* __restrict__ dst, int n) {
    int i = blockIdx.x * blockDim.x + threadIdx.x;
    if (i < n) dst[i] = src[i];
}

// ==================== conv3: i2h for ALL timesteps ====================
// 16 oc/block, 2x2 px/thread, 32x32 tile, double-buffered staging,
// vectorized smem reads (window LDS.64, weights padded to 12 -> LDS.128).
// grid (9, 12, SEQ*BB), block (16,16)
__global__ void __launch_bounds__(256, 2)
conv3_kernel(const float* __restrict__ x, const float* __restrict__ w,
             const float* __restrict__ bias)
{
    __shared__ __align__(16) float sm[2][34 * 34];
    __shared__ __align__(16) float sw[CIN * 16 * 12];   // [ic][o][12], pad 9->12

    int sb  = blockIdx.z;
    int ocg = blockIdx.y;
    int tileY = (blockIdx.x / 3) * 32;
    int tileX = (blockIdx.x % 3) * 32;
    int tid = threadIdx.y * 16 + threadIdx.x;

    for (int i = tid; i < CIN * 16 * 12; i += 256) {
        int ic = i / 192, rem = i % 192;
        int o = rem / 12, k = rem % 12;
        sw[i] = (k < 9) ? w[((ocg * 16 + o) * CIN + ic) * 9 + k] : 0.f;
    }

    const float* xb = x + (size_t)sb * CIN * HW;

    float rbuf[5];
#define C3_LD(IC) { \
        const float* src = xb + (size_t)(IC) * HW; \
        _Pragma("unroll") \
        for (int k = 0; k < 5; k++) { \
            int i = tid + k * 256; float v = 0.f; \
            if (i < 34 * 34) { \
                int r = i / 34, c = i % 34; \
                int gy = tileY + r - 1, gx = tileX + c - 1; \
                if ((unsigned)gy < (unsigned)HH && (unsigned)gx < (unsigned)WW) \
                    v = src[gy * WW + gx]; \
            } \
            rbuf[k] = v; \
        } }
#define C3_ST(BUF) { \
        _Pragma("unroll") \
        for (int k = 0; k < 5; k++) { \
            int i = tid + k * 256; \
            if (i < 34 * 34) sm[BUF][i] = rbuf[k]; \
        } }

    float acc[16][4];
#pragma unroll
    for (int o = 0; o < 16; o++)
#pragma unroll
        for (int p = 0; p < 4; p++) acc[o][p] = 0.f;

    C3_LD(0);
    int buf = 0;
    for (int ic = 0; ic < CIN; ic++) {
        C3_ST(buf);
        __syncthreads();
        if (ic + 1 < CIN) C3_LD(ic + 1);

        int ry = threadIdx.y * 2, rx = threadIdx.x * 2;
        float win[4][4];
#pragma unroll
        for (int i = 0; i < 4; i++) {
            float2 a = *(const float2*)&sm[buf][(ry + i) * 34 + rx];
            float2 bq = *(const float2*)&sm[buf][(ry + i) * 34 + rx + 2];
            win[i][0] = a.x; win[i][1] = a.y; win[i][2] = bq.x; win[i][3] = bq.y;
        }

#pragma unroll
        for (int o = 0; o < 16; o++) {
            float wv[12];
#pragma unroll
            for (int q = 0; q < 3; q++)
                *(float4*)&wv[q * 4] = *(const float4*)&sw[(ic * 16 + o) * 12 + q * 4];
#pragma unroll
            for (int py = 0; py < 2; py++)
#pragma unroll
                for (int px = 0; px < 2; px++) {
                    acc[o][py*2+px] +=
                        win[py  ][px]*wv[0] + win[py  ][px+1]*wv[1] + win[py  ][px+2]*wv[2]
                      + win[py+1][px]*wv[3] + win[py+1][px+1]*wv[4] + win[py+1][px+2]*wv[5]
                      + win[py+2][px]*wv[6] + win[py+2][px+1]*wv[7] + win[py+2][px+2]*wv[8];
                }
        }
        buf ^= 1;
    }
#undef C3_LD
#undef C3_ST

    int oy = tileY + threadIdx.y * 2, ox = tileX + threadIdx.x * 2;
#pragma unroll
    for (int o = 0; o < 16; o++) {
        float bv = bias[ocg * 16 + o];
        float* yp = g_i2h + ((size_t)sb * C3 + ocg * 16 + o) * HW;
        yp[oy * WW + ox]           = acc[o][0] + bv;
        yp[oy * WW + ox + 1]       = acc[o][1] + bv;
        yp[(oy + 1) * WW + ox]     = acc[o][2] + bv;
        yp[(oy + 1) * WW + ox + 1] = acc[o][3] + bv;
    }
}

// ==================== fused f conv: tanh(conv5(x) + conv5(h_prev)) ====================
// 8 oc/block, 2x2 px/thread, double-buffered; window LDS.64, weights padded 25->28.
// grid (9, 4, BB), block (16,16)
__global__ void __launch_bounds__(256, 2)
conv5_f_kernel(const float* __restrict__ x, const float* __restrict__ hp,
               const float* __restrict__ i2f_w, const float* __restrict__ h2f_w,
               const float* __restrict__ i2f_b, const float* __restrict__ h2f_b,
               int skip_h)
{
    __shared__ __align__(16) float sm[2][36 * 36];
    __shared__ __align__(16) float sw[2][8 * 28];

    int b   = blockIdx.z;
    int ocg = blockIdx.y;
    int tileY = (blockIdx.x / 3) * 32;
    int tileX = (blockIdx.x % 3) * 32;
    int tid = threadIdx.y * 16 + threadIdx.x;

    float acc[8][4];
#pragma unroll
    for (int o = 0; o < 8; o++)
#pragma unroll
        for (int p = 0; p < 4; p++) acc[o][p] = 0.f;

    int ctot = skip_h ? CIN : (CIN + NF);

    float rbuf[6], wreg = 0.f;
#define F_LD(IC) { \
        const float* src; const float* wsrc; int cnum, icl; \
        if ((IC) < CIN) { src = x + ((size_t)b * CIN + (IC)) * HW; wsrc = i2f_w; cnum = CIN; icl = (IC); } \
        else { src = hp + ((size_t)b * NF + ((IC) - CIN)) * HW; wsrc = h2f_w; cnum = NF; icl = (IC) - CIN; } \
        _Pragma("unroll") \
        for (int k = 0; k < 6; k++) { \
            int i = tid + k * 256; float v = 0.f; \
            if (i < 36 * 36) { \
                int r = i / 36, c = i % 36; \
                int gy = tileY + r - 2, gx = tileX + c - 2; \
                if ((unsigned)gy < (unsigned)HH && (unsigned)gx < (unsigned)WW) \
                    v = src[gy * WW + gx]; \
            } \
            rbuf[k] = v; \
        } \
        if (tid < 224) { \
            int o = tid / 28, kk = tid % 28; \
            wreg = (kk < 25) ? wsrc[((size_t)(ocg * 8 + o) * cnum + icl) * 25 + kk] : 0.f; \
        } }
#define F_ST(BUF) { \
        _Pragma("unroll") \
        for (int k = 0; k < 6; k++) { \
            int i = tid + k * 256; \
            if (i < 36 * 36) sm[BUF][i] = rbuf[k]; \
        } \
        if (tid < 224) sw[BUF][tid] = wreg; }

    F_LD(0);
    int buf = 0;
    for (int ic = 0; ic < ctot; ic++) {
        F_ST(buf);
        __syncthreads();
        if (ic + 1 < ctot) F_LD(ic + 1);

        int ry = threadIdx.y * 2, rx = threadIdx.x * 2;
        float win[6][6];
#pragma unroll
        for (int i = 0; i < 6; i++) {
            float2 a = *(const float2*)&sm[buf][(ry + i) * 36 + rx];
            float2 bq = *(const float2*)&sm[buf][(ry + i) * 36 + rx + 2];
            float2 cq = *(const float2*)&sm[buf][(ry + i) * 36 + rx + 4];
            win[i][0] = a.x;  win[i][1] = a.y;
            win[i][2] = bq.x; win[i][3] = bq.y;
            win[i][4] = cq.x; win[i][5] = cq.y;
        }

#pragma unroll
        for (int o = 0; o < 8; o++) {
            float wv[28];
#pragma unroll
            for (int q = 0; q < 7; q++)
                *(float4*)&wv[q * 4] = *(const float4*)&sw[buf][o * 28 + q * 4];
#pragma unroll
            for (int ky = 0; ky < 5; ky++)
#pragma unroll
                for (int kx = 0; kx < 5; kx++) {
                    float wvv = wv[ky * 5 + kx];
                    acc[o][0] += win[ky  ][kx  ] * wvv;
                    acc[o][1] += win[ky  ][kx+1] * wvv;
                    acc[o][2] += win[ky+1][kx  ] * wvv;
                    acc[o][3] += win[ky+1][kx+1] * wvv;
                }
        }
        buf ^= 1;
    }
#undef F_LD
#undef F_ST

    int oy = tileY + threadIdx.y * 2, ox = tileX + threadIdx.x * 2;
#pragma unroll
    for (int o = 0; o < 8; o++) {
        int oc = ocg * 8 + o;
        float bv = i2f_b[oc] + h2f_b[oc];
        float* yp = g_f + ((size_t)b * CF + oc) * HW;
        yp[oy * WW + ox]           = ftanh(acc[o][0] + bv);
        yp[oy * WW + ox + 1]       = ftanh(acc[o][1] + bv);
        yp[(oy + 1) * WW + ox]     = ftanh(acc[o][2] + bv);
        yp[(oy + 1) * WW + ox + 1] = ftanh(acc[o][3] + bv);
    }
}

// ==================== flows conv: conv5(g_f) -> g_flows ====================
// all 10 oc, 2x2 px/thread; all weights preloaded padded (10*32*28 floats = 35KB).
// grid (9, 1, BB), block (16,16)
__global__ void __launch_bounds__(256, 2)
conv5_flows_kernel(const float* __restrict__ flows_w, const float* __restrict__ flows_b)
{
    __shared__ __align__(16) float sm[2][36 * 36];
    __shared__ __align__(16) float sw[CFL * CF * 28];   // [o][ic][28]

    int b = blockIdx.z;
    int tileY = (blockIdx.x / 3) * 32;
    int tileX = (blockIdx.x % 3) * 32;
    int tid = threadIdx.y * 16 + threadIdx.x;

    for (int i = tid; i < CFL * CF * 28; i += 256) {
        int k = i % 28;
        int oc_ic = i / 28;
        sw[i] = (k < 25) ? flows_w[oc_ic * 25 + k] : 0.f;
    }

    float acc[CFL][4];
#pragma unroll
    for (int o = 0; o < CFL; o++)
#pragma unroll
        for (int p = 0; p < 4; p++) acc[o][p] = 0.f;

    float rbuf[6];
#define FL_LD(IC) { \
        const float* src = g_f + ((size_t)b * CF + (IC)) * HW; \
        _Pragma("unroll") \
        for (int k = 0; k < 6; k++) { \
            int i = tid + k * 256; float v = 0.f; \
            if (i < 36 * 36) { \
                int r = i / 36, c = i % 36; \
                int gy = tileY + r - 2, gx = tileX + c - 2; \
                if ((unsigned)gy < (unsigned)HH && (unsigned)gx < (unsigned)WW) \
                    v = src[gy * WW + gx]; \
            } \
            rbuf[k] = v; \
        } }
#define FL_ST(BUF) { \
        _Pragma("unroll") \
        for (int k = 0; k < 6; k++) { \
            int i = tid + k * 256; \
            if (i < 36 * 36) sm[BUF][i] = rbuf[k]; \
        } }

    FL_LD(0);
    int buf = 0;
    for (int ic = 0; ic < CF; ic++) {
        FL_ST(buf);
        __syncthreads();
        if (ic + 1 < CF) FL_LD(ic + 1);

        int ry = threadIdx.y * 2, rx = threadIdx.x * 2;
        float win[6][6];
#pragma unroll
        for (int i = 0; i < 6; i++) {
            float2 a = *(const float2*)&sm[buf][(ry + i) * 36 + rx];
            float2 bq = *(const float2*)&sm[buf][(ry + i) * 36 + rx + 2];
            float2 cq = *(const float2*)&sm[buf][(ry + i) * 36 + rx + 4];
            win[i][0] = a.x;  win[i][1] = a.y;
            win[i][2] = bq.x; win[i][3] = bq.y;
            win[i][4] = cq.x; win[i][5] = cq.y;
        }

#pragma unroll
        for (int o = 0; o < CFL; o++) {
            float wv[28];
#pragma unroll
            for (int q = 0; q < 7; q++)
                *(float4*)&wv[q * 4] = *(const float4*)&sw[(o * CF + ic) * 28 + q * 4];
#pragma unroll
            for (int ky = 0; ky < 5; ky++)
#pragma unroll
                for (int kx = 0; kx < 5; kx++) {
                    float wvv = wv[ky * 5 + kx];
                    acc[o][0] += win[ky  ][kx  ] * wvv;
                    acc[o][1] += win[ky  ][kx+1] * wvv;
                    acc[o][2] += win[ky+1][kx  ] * wvv;
                    acc[o][3] += win[ky+1][kx+1] * wvv;
                }
        }
        buf ^= 1;
    }
#undef FL_LD
#undef FL_ST

    int oy = tileY + threadIdx.y * 2, ox = tileX + threadIdx.x * 2;
#pragma unroll
    for (int o = 0; o < CFL; o++) {
        float bv = flows_b[o];
        float* yp = g_flows + ((size_t)b * CFL + o) * HW;
        yp[oy * WW + ox]           = acc[o][0] + bv;
        yp[oy * WW + ox + 1]       = acc[o][1] + bv;
        yp[(oy + 1) * WW + ox]     = acc[o][2] + bv;
        yp[(oy + 1) * WW + ox + 1] = acc[o][3] + bv;
    }
}

// ==================== bilinear warp -> g_warp ====================
__global__ void warp_kernel(const float* __restrict__ hp)
{
    int idx = blockIdx.x * blockDim.x + threadIdx.x;
    const int total = BB * LL * HW;
    if (idx >= total) return;

    int pix = idx % HW;
    int bl  = idx / HW;
    int l = bl % LL;
    int b = bl / LL;
    int gx = pix % WW;
    int gy = pix / WW;

    const float* fl = g_flows + ((size_t)b * CFL + 2 * l) * HW;
    float fx = fl[pix];
    float fy = fl[HW + pix];

    float vx = (float)gx - fx;
    float vy = (float)gy - fy;
    float gxn = 2.f * vx / (float)(WW - 1) - 1.f;
    float gyn = 2.f * vy / (float)(HH - 1) - 1.f;
    float sx = ((gxn + 1.f) * (float)WW - 1.f) * 0.5f;
    float sy = ((gyn + 1.f) * (float)HH - 1.f) * 0.5f;

    float x0f = floorf(sx), y0f = floorf(sy);
    int x0 = (int)x0f, y0 = (int)y0f;
    int x1 = x0 + 1, y1 = y0 + 1;
    float wx1 = sx - x0f, wx0 = 1.f - wx1;
    float wy1 = sy - y0f, wy0 = 1.f - wy1;

    bool vx0 = (x0 >= 0) && (x0 < WW);
    bool vx1 = (x1 >= 0) && (x1 < WW);
    bool vy0 = (y0 >= 0) && (y0 < HH);
    bool vy1 = (y1 >= 0) && (y1 < HH);

    int xc0 = min(max(x0, 0), WW - 1);
    int xc1 = min(max(x1, 0), WW - 1);
    int yc0 = min(max(y0, 0), HH - 1);
    int yc1 = min(max(y1, 0), HH - 1);

    float w00 = (vy0 && vx0) ? wy0 * wx0 : 0.f;
    float w01 = (vy0 && vx1) ? wy0 * wx1 : 0.f;
    float w10 = (vy1 && vx0) ? wy1 * wx0 : 0.f;
    float w11 = (vy1 && vx1) ? wy1 * wx1 : 0.f;

    int o00 = yc0 * WW + xc0;
    int o01 = yc0 * WW + xc1;
    int o10 = yc1 * WW + xc0;
    int o11 = yc1 * WW + xc1;

    const float* hb = hp + (size_t)b * NF * HW;
    float* ob = g_warp + ((size_t)b * KW + (size_t)l * NF) * HW + pix;

#pragma unroll 8
    for (int c = 0; c < NF; c++) {
        const float* hc = hb + (size_t)c * HW;
        float v = w00 * __ldg(hc + o00) + w01 * __ldg(hc + o01)
                + w10 * __ldg(hc + o10) + w11 * __ldg(hc + o11);
        ob[(size_t)c * HW] = v;
    }
}

// ==================== 1x1 conv GEMM: g_h2h = ret_w @ g_warp + ret_b ====================
// M=192, K=320, N=9216. BM=64, BN=128, BK=16, 256 threads, 4x8 microtile, double-buffered.
__global__ void __launch_bounds__(256, 2)
gemm_kernel(const float* __restrict__ Wm, const float* __restrict__ bias)
{
    const int M = C3, K = KW, N = HW;
    __shared__ __align__(16) float Ws[2][16][64];
    __shared__ __align__(16) float As[2][16][128];

    int b  = blockIdx.z;
    int m0 = blockIdx.y * 64;
    int n0 = blockIdx.x * 128;
    int tid = threadIdx.x;
    int tx = tid % 16;
    int ty = tid / 16;

    const float* Ab = g_warp + (size_t)b * K * N;

    float acc[4][8];
#pragma unroll
    for (int i = 0; i < 4; i++)
#pragma unroll
        for (int j = 0; j < 8; j++) acc[i][j] = 0.f;

    int arow = tid / 16;
    int acol = (tid % 16) * 8;

    float4 pa0, pa1;
    float pw[4];

#define G_LD(K0) { \
        const float* ap = Ab + (size_t)((K0) + arow) * N + n0 + acol; \
        pa0 = *(const float4*)(ap); \
        pa1 = *(const float4*)(ap + 4); \
        _Pragma("unroll") \
        for (int r = 0; r < 4; r++) { \
            int i = tid + r * 256; \
            int m = i / 16, kk = i % 16; \
            pw[r] = Wm[(size_t)(m0 + m) * K + (K0) + kk]; \
        } }
#define G_ST(BUF) { \
        *(float4*)&As[BUF][arow][acol]     = pa0; \
        *(float4*)&As[BUF][arow][acol + 4] = pa1; \
        _Pragma("unroll") \
        for (int r = 0; r < 4; r++) { \
            int i = tid + r * 256; \
            int m = i / 16, kk = i % 16; \
            Ws[BUF][kk][m] = pw[r]; \
        } }

    G_LD(0);
    int buf = 0;
    for (int k0 = 0; k0 < K; k0 += 16) {
        G_ST(buf);
        __syncthreads();
        if (k0 + 16 < K) G_LD(k0 + 16);

#pragma unroll
        for (int kk = 0; kk < 16; kk++) {
            float4 av = *(const float4*)&Ws[buf][kk][ty * 4];
            float4 b0 = *(const float4*)&As[buf][kk][tx * 8];
            float4 b1 = *(const float4*)&As[buf][kk][tx * 8 + 4];
            acc[0][0] += av.x*b0.x; acc[0][1] += av.x*b0.y; acc[0][2] += av.x*b0.z; acc[0][3] += av.x*b0.w;
            acc[0][4] += av.x*b1.x; acc[0][5] += av.x*b1.y; acc[0][6] += av.x*b1.z; acc[0][7] += av.x*b1.w;
            acc[1][0] += av.y*b0.x; acc[1][1] += av.y*b0.y; acc[1][2] += av.y*b0.z; acc[1][3] += av.y*b0.w;
            acc[1][4] += av.y*b1.x; acc[1][5] += av.y*b1.y; acc[1][6] += av.y*b1.z; acc[1][7] += av.y*b1.w;
            acc[2][0] += av.z*b0.x; acc[2][1] += av.z*b0.y; acc[2][2] += av.z*b0.z; acc[2][3] += av.z*b0.w;
            acc[2][4] += av.z*b1.x; acc[2][5] += av.z*b1.y; acc[2][6] += av.z*b1.z; acc[2][7] += av.z*b1.w;
            acc[3][0] += av.w*b0.x; acc[3][1] += av.w*b0.y; acc[3][2] += av.w*b0.z; acc[3][3] += av.w*b0.w;
            acc[3][4] += av.w*b1.x; acc[3][5] += av.w*b1.y; acc[3][6] += av.w*b1.z; acc[3][7] += av.w*b1.w;
        }
        buf ^= 1;
    }
#undef G_LD
#undef G_ST

    float* Cb = g_h2h + (size_t)b * M * N;
#pragma unroll
    for (int i = 0; i < 4; i++) {
        int m = m0 + ty * 4 + i;
        float bvv = bias[m];
        float4 c0 = make_float4(acc[i][0]+bvv, acc[i][1]+bvv, acc[i][2]+bvv, acc[i][3]+bvv);
        float4 c1 = make_float4(acc[i][4]+bvv, acc[i][5]+bvv, acc[i][6]+bvv, acc[i][7]+bvv);
        *(float4*)&Cb[(size_t)m * N + n0 + tx * 8]     = c0;
        *(float4*)&Cb[(size_t)m * N + n0 + tx * 8 + 4] = c1;
    }
}

// ==================== gates (elementwise GRU update, float4) ====================
__global__ void gates_kernel(int t, const float* __restrict__ hp,
                             float* __restrict__ hn, const float* __restrict__ ret_b, int first)
{
    int idx = blockIdx.x * blockDim.x + threadIdx.x;
    const int total4 = BB * NF * HW / 4;
    if (idx >= total4) return;

    const float* i2h_t = g_i2h + (size_t)t * BB * C3 * HW;

    int e = idx * 4;
    int pix = e % HW;
    int rest = e / HW;
    int c = rest % NF;
    int b = rest / NF;

    size_t base = ((size_t)b * C3 + c) * HW + pix;
    float4 ir = *(const float4*)&i2h_t[base];
    float4 iu = *(const float4*)&i2h_t[base + (size_t)NF * HW];
    float4 im = *(const float4*)&i2h_t[base + (size_t)2 * NF * HW];

    float4 hr, hu, hm, hpv;
    if (first) {
        float r0 = ret_b[c], u0 = ret_b[c + NF], m0 = ret_b[c + 2 * NF];
        hr = make_float4(r0, r0, r0, r0);
        hu = make_float4(u0, u0, u0, u0);
        hm = make_float4(m0, m0, m0, m0);
        hpv = make_float4(0.f, 0.f, 0.f, 0.f);
    } else {
        hr = *(const float4*)&g_h2h[base];
        hu = *(const float4*)&g_h2h[base + (size_t)NF * HW];
        hm = *(const float4*)&g_h2h[base + (size_t)2 * NF * HW];
        hpv = *(const float4*)&hp[((size_t)b * NF + c) * HW + pix];
    }

    float4 outv;
#define GATE1(X) { \
        float r = fsigmoid(ir.X + hr.X); \
        float u = fsigmoid(iu.X + hu.X); \
        float m = ftanh(im.X + r * hm.X); \
        outv.X = u * hpv.X + (1.f - u) * m; }
    GATE1(x) GATE1(y) GATE1(z) GATE1(w)
#undef GATE1

    *(float4*)&hn[((size_t)b * NF + c) * HW + pix] = outv;
}

// -------------------- launcher --------------------
extern "C" void kernel_launch(void* const* d_in, const int* in_sizes, int n_in,
                              void* d_out, int out_size)
{
    const float* inputs  = (const float*)d_in[0];
    const float* i2h_w   = (const float*)d_in[1];
    const float* i2h_b   = (const float*)d_in[2];
    const float* i2f_w   = (const float*)d_in[3];
    const float* i2f_b   = (const float*)d_in[4];
    const float* h2f_w   = (const float*)d_in[5];
    const float* h2f_b   = (const float*)d_in[6];
    const float* flows_w = (const float*)d_in[7];
    const float* flows_b = (const float*)d_in[8];
    const float* ret_w   = (const float*)d_in[9];
    const float* ret_b   = (const float*)d_in[10];
    float* out = (float*)d_out;

    const int hstride = BB * NF * HW;
    const dim3 thr16(16, 16);

    conv3_kernel<<<dim3(9, C3 / 16, SEQ * BB), thr16>>>(inputs, i2h_w, i2h_b);

    for (int t = 0; t < SEQ; t++) {
        const float* x_t   = inputs + (size_t)t * BB * CIN * HW;
        const float* hprev = (t == 0) ? nullptr : out + (size_t)(t - 1) * hstride;
        float* hnew        = out + (size_t)t * hstride;
        int first = (t == 0) ? 1 : 0;

        conv5_f_kernel<<<dim3(9, CF / 8, BB), thr16>>>(x_t, hprev, i2f_w, h2f_w,
                                                       i2f_b, h2f_b, first);

        if (!first) {
            conv5_flows_kernel<<<dim3(9, 1, BB), thr16>>>(flows_w, flows_b);
            warp_kernel<<<(BB * LL * HW + 255) / 256, 256>>>(hprev);
            gemm_kernel<<<dim3(HW / 128, C3 / 64, BB), 256>>>(ret_w, ret_b);
        }

        gates_kernel<<<(hstride / 4 + 255) / 256, 256>>>(t, hprev, hnew, ret_b, first);
    }

    if (out_size >= (SEQ + 1) * hstride) {
        copy_kernel<<<(hstride + 255) / 256, 256>>>(out + (size_t)(SEQ - 1) * hstride,
                                                    out + (size_t)SEQ * hstride, hstride);
    }
}

// round 10
// speedup vs baseline: 1.1119x; 1.1119x over previous
#include <cuda_runtime.h>
#include <cuda_bf16.h>
#include <math.h>

// Problem constants (fixed shapes)
#define SEQ   8
#define BB    8
#define CIN   16
#define HH    96
#define WW    96
#define HW    (HH*WW)      // 9216
#define NF    64
#define LL    5
#define C3    (3*NF)       // 192
#define CF    32           // f channels
#define CFL   (2*LL)       // 10 flow channels
#define KW    (LL*NF)      // 320 warped channels

// -------------------- scratch (device globals; no allocation) --------------------
__device__ float g_i2h  [(size_t)SEQ * BB * C3 * HW];
__device__ float g_f    [(size_t)BB * CF  * HW];
__device__ float g_flows[(size_t)BB * CFL * HW];
__device__ float g_warp [(size_t)BB * KW  * HW];

// fast transcendentals (accuracy budget is 1e-3; these are ~1e-7 level here)
__device__ __forceinline__ float fsigmoid(float x) {
    return 1.f / (1.f + __expf(-x));
}
__device__ __forceinline__ float ftanh(float x) {
    float e = __expf(2.f * x);
    return (e - 1.f) / (e + 1.f);
}

// -------------------- utility --------------------
__global__ void copy_kernel(const float* __restrict__ src, float* __restrict__ dst, int n) {
    int i = blockIdx.x * blockDim.x + threadIdx.x;
    if (i < n) dst[i] = src[i];
}

// ==================== conv3: i2h for ALL timesteps ====================
// 16 oc/block, 2x2 px/thread, 32x32 tile, double-buffered staging.
// grid (9, 12, SEQ*BB), block (16,16)
__global__ void __launch_bounds__(256, 2)
conv3_kernel(const float* __restrict__ x, const float* __restrict__ w,
             const float* __restrict__ bias)
{
    __shared__ __align__(16) float sm[2][34 * 34];
    __shared__ __align__(16) float sw[CIN * 16 * 12];   // [ic][o][12], pad 9->12

    int sb  = blockIdx.z;
    int ocg = blockIdx.y;
    int tileY = (blockIdx.x / 3) * 32;
    int tileX = (blockIdx.x % 3) * 32;
    int tid = threadIdx.y * 16 + threadIdx.x;

    for (int i = tid; i < CIN * 16 * 12; i += 256) {
        int ic = i / 192, rem = i % 192;
        int o = rem / 12, k = rem % 12;
        sw[i] = (k < 9) ? w[((ocg * 16 + o) * CIN + ic) * 9 + k] : 0.f;
    }

    const float* xb = x + (size_t)sb * CIN * HW;

    float rbuf[5];
#define C3_LD(IC) { \
        const float* src = xb + (size_t)(IC) * HW; \
        _Pragma("unroll") \
        for (int k = 0; k < 5; k++) { \
            int i = tid + k * 256; float v = 0.f; \
            if (i < 34 * 34) { \
                int r = i / 34, c = i % 34; \
                int gy = tileY + r - 1, gx = tileX + c - 1; \
                if ((unsigned)gy < (unsigned)HH && (unsigned)gx < (unsigned)WW) \
                    v = src[gy * WW + gx]; \
            } \
            rbuf[k] = v; \
        } }
#define C3_ST(BUF) { \
        _Pragma("unroll") \
        for (int k = 0; k < 5; k++) { \
            int i = tid + k * 256; \
            if (i < 34 * 34) sm[BUF][i] = rbuf[k]; \
        } }

    float acc[16][4];
#pragma unroll
    for (int o = 0; o < 16; o++)
#pragma unroll
        for (int p = 0; p < 4; p++) acc[o][p] = 0.f;

    C3_LD(0);
    int buf = 0;
    for (int ic = 0; ic < CIN; ic++) {
        C3_ST(buf);
        __syncthreads();
        if (ic + 1 < CIN) C3_LD(ic + 1);

        int ry = threadIdx.y * 2, rx = threadIdx.x * 2;
        float win[4][4];
#pragma unroll
        for (int i = 0; i < 4; i++) {
            float2 a = *(const float2*)&sm[buf][(ry + i) * 34 + rx];
            float2 bq = *(const float2*)&sm[buf][(ry + i) * 34 + rx + 2];
            win[i][0] = a.x; win[i][1] = a.y; win[i][2] = bq.x; win[i][3] = bq.y;
        }

#pragma unroll
        for (int o = 0; o < 16; o++) {
            float wv[12];
#pragma unroll
            for (int q = 0; q < 3; q++)
                *(float4*)&wv[q * 4] = *(const float4*)&sw[(ic * 16 + o) * 12 + q * 4];
#pragma unroll
            for (int py = 0; py < 2; py++)
#pragma unroll
                for (int px = 0; px < 2; px++) {
                    acc[o][py*2+px] +=
                        win[py  ][px]*wv[0] + win[py  ][px+1]*wv[1] + win[py  ][px+2]*wv[2]
                      + win[py+1][px]*wv[3] + win[py+1][px+1]*wv[4] + win[py+1][px+2]*wv[5]
                      + win[py+2][px]*wv[6] + win[py+2][px+1]*wv[7] + win[py+2][px+2]*wv[8];
                }
        }
        buf ^= 1;
    }
#undef C3_LD
#undef C3_ST

    int oy = tileY + threadIdx.y * 2, ox = tileX + threadIdx.x * 2;
#pragma unroll
    for (int o = 0; o < 16; o++) {
        float bv = bias[ocg * 16 + o];
        float* yp = g_i2h + ((size_t)sb * C3 + ocg * 16 + o) * HW;
        yp[oy * WW + ox]           = acc[o][0] + bv;
        yp[oy * WW + ox + 1]       = acc[o][1] + bv;
        yp[(oy + 1) * WW + ox]     = acc[o][2] + bv;
        yp[(oy + 1) * WW + ox + 1] = acc[o][3] + bv;
    }
}

// ==================== fused f conv: tanh(conv5(x) + conv5(h_prev)) ====================
// 8 oc/block, 2x2 px/thread, double-buffered; window LDS.64, weights padded 25->28.
// grid (9, 4, BB), block (16,16)
__global__ void __launch_bounds__(256, 2)
conv5_f_kernel(const float* __restrict__ x, const float* __restrict__ hp,
               const float* __restrict__ i2f_w, const float* __restrict__ h2f_w,
               const float* __restrict__ i2f_b, const float* __restrict__ h2f_b,
               int skip_h)
{
    __shared__ __align__(16) float sm[2][36 * 36];
    __shared__ __align__(16) float sw[2][8 * 28];

    int b   = blockIdx.z;
    int ocg = blockIdx.y;
    int tileY = (blockIdx.x / 3) * 32;
    int tileX = (blockIdx.x % 3) * 32;
    int tid = threadIdx.y * 16 + threadIdx.x;

    float acc[8][4];
#pragma unroll
    for (int o = 0; o < 8; o++)
#pragma unroll
        for (int p = 0; p < 4; p++) acc[o][p] = 0.f;

    int ctot = skip_h ? CIN : (CIN + NF);

    float rbuf[6], wreg = 0.f;
#define F_LD(IC) { \
        const float* src; const float* wsrc; int cnum, icl; \
        if ((IC) < CIN) { src = x + ((size_t)b * CIN + (IC)) * HW; wsrc = i2f_w; cnum = CIN; icl = (IC); } \
        else { src = hp + ((size_t)b * NF + ((IC) - CIN)) * HW; wsrc = h2f_w; cnum = NF; icl = (IC) - CIN; } \
        _Pragma("unroll") \
        for (int k = 0; k < 6; k++) { \
            int i = tid + k * 256; float v = 0.f; \
            if (i < 36 * 36) { \
                int r = i / 36, c = i % 36; \
                int gy = tileY + r - 2, gx = tileX + c - 2; \
                if ((unsigned)gy < (unsigned)HH && (unsigned)gx < (unsigned)WW) \
                    v = src[gy * WW + gx]; \
            } \
            rbuf[k] = v; \
        } \
        if (tid < 224) { \
            int o = tid / 28, kk = tid % 28; \
            wreg = (kk < 25) ? wsrc[((size_t)(ocg * 8 + o) * cnum + icl) * 25 + kk] : 0.f; \
        } }
#define F_ST(BUF) { \
        _Pragma("unroll") \
        for (int k = 0; k < 6; k++) { \
            int i = tid + k * 256; \
            if (i < 36 * 36) sm[BUF][i] = rbuf[k]; \
        } \
        if (tid < 224) sw[BUF][tid] = wreg; }

    F_LD(0);
    int buf = 0;
    for (int ic = 0; ic < ctot; ic++) {
        F_ST(buf);
        __syncthreads();
        if (ic + 1 < ctot) F_LD(ic + 1);

        int ry = threadIdx.y * 2, rx = threadIdx.x * 2;
        float win[6][6];
#pragma unroll
        for (int i = 0; i < 6; i++) {
            float2 a = *(const float2*)&sm[buf][(ry + i) * 36 + rx];
            float2 bq = *(const float2*)&sm[buf][(ry + i) * 36 + rx + 2];
            float2 cq = *(const float2*)&sm[buf][(ry + i) * 36 + rx + 4];
            win[i][0] = a.x;  win[i][1] = a.y;
            win[i][2] = bq.x; win[i][3] = bq.y;
            win[i][4] = cq.x; win[i][5] = cq.y;
        }

#pragma unroll
        for (int o = 0; o < 8; o++) {
            float wv[28];
#pragma unroll
            for (int q = 0; q < 7; q++)
                *(float4*)&wv[q * 4] = *(const float4*)&sw[buf][o * 28 + q * 4];
#pragma unroll
            for (int ky = 0; ky < 5; ky++)
#pragma unroll
                for (int kx = 0; kx < 5; kx++) {
                    float wvv = wv[ky * 5 + kx];
                    acc[o][0] += win[ky  ][kx  ] * wvv;
                    acc[o][1] += win[ky  ][kx+1] * wvv;
                    acc[o][2] += win[ky+1][kx  ] * wvv;
                    acc[o][3] += win[ky+1][kx+1] * wvv;
                }
        }
        buf ^= 1;
    }
#undef F_LD
#undef F_ST

    int oy = tileY + threadIdx.y * 2, ox = tileX + threadIdx.x * 2;
#pragma unroll
    for (int o = 0; o < 8; o++) {
        int oc = ocg * 8 + o;
        float bv = i2f_b[oc] + h2f_b[oc];
        float* yp = g_f + ((size_t)b * CF + oc) * HW;
        yp[oy * WW + ox]           = ftanh(acc[o][0] + bv);
        yp[oy * WW + ox + 1]       = ftanh(acc[o][1] + bv);
        yp[(oy + 1) * WW + ox]     = ftanh(acc[o][2] + bv);
        yp[(oy + 1) * WW + ox + 1] = ftanh(acc[o][3] + bv);
    }
}

// ==================== flows conv: conv5(g_f) -> g_flows ====================
// all 10 oc, 2x2 px/thread; all weights preloaded padded.
// grid (9, 1, BB), block (16,16)
__global__ void __launch_bounds__(256, 2)
conv5_flows_kernel(const float* __restrict__ flows_w, const float* __restrict__ flows_b)
{
    __shared__ __align__(16) float sm[2][36 * 36];
    __shared__ __align__(16) float sw[CFL * CF * 28];

    int b = blockIdx.z;
    int tileY = (blockIdx.x / 3) * 32;
    int tileX = (blockIdx.x % 3) * 32;
    int tid = threadIdx.y * 16 + threadIdx.x;

    for (int i = tid; i < CFL * CF * 28; i += 256) {
        int k = i % 28;
        int oc_ic = i / 28;
        sw[i] = (k < 25) ? flows_w[oc_ic * 25 + k] : 0.f;
    }

    float acc[CFL][4];
#pragma unroll
    for (int o = 0; o < CFL; o++)
#pragma unroll
        for (int p = 0; p < 4; p++) acc[o][p] = 0.f;

    float rbuf[6];
#define FL_LD(IC) { \
        const float* src = g_f + ((size_t)b * CF + (IC)) * HW; \
        _Pragma("unroll") \
        for (int k = 0; k < 6; k++) { \
            int i = tid + k * 256; float v = 0.f; \
            if (i < 36 * 36) { \
                int r = i / 36, c = i % 36; \
                int gy = tileY + r - 2, gx = tileX + c - 2; \
                if ((unsigned)gy < (unsigned)HH && (unsigned)gx < (unsigned)WW) \
                    v = src[gy * WW + gx]; \
            } \
            rbuf[k] = v; \
        } }
#define FL_ST(BUF) { \
        _Pragma("unroll") \
        for (int k = 0; k < 6; k++) { \
            int i = tid + k * 256; \
            if (i < 36 * 36) sm[BUF][i] = rbuf[k]; \
        } }

    FL_LD(0);
    int buf = 0;
    for (int ic = 0; ic < CF; ic++) {
        FL_ST(buf);
        __syncthreads();
        if (ic + 1 < CF) FL_LD(ic + 1);

        int ry = threadIdx.y * 2, rx = threadIdx.x * 2;
        float win[6][6];
#pragma unroll
        for (int i = 0; i < 6; i++) {
            float2 a = *(const float2*)&sm[buf][(ry + i) * 36 + rx];
            float2 bq = *(const float2*)&sm[buf][(ry + i) * 36 + rx + 2];
            float2 cq = *(const float2*)&sm[buf][(ry + i) * 36 + rx + 4];
            win[i][0] = a.x;  win[i][1] = a.y;
            win[i][2] = bq.x; win[i][3] = bq.y;
            win[i][4] = cq.x; win[i][5] = cq.y;
        }

#pragma unroll
        for (int o = 0; o < CFL; o++) {
            float wv[28];
#pragma unroll
            for (int q = 0; q < 7; q++)
                *(float4*)&wv[q * 4] = *(const float4*)&sw[(o * CF + ic) * 28 + q * 4];
#pragma unroll
            for (int ky = 0; ky < 5; ky++)
#pragma unroll
                for (int kx = 0; kx < 5; kx++) {
                    float wvv = wv[ky * 5 + kx];
                    acc[o][0] += win[ky  ][kx  ] * wvv;
                    acc[o][1] += win[ky  ][kx+1] * wvv;
                    acc[o][2] += win[ky+1][kx  ] * wvv;
                    acc[o][3] += win[ky+1][kx+1] * wvv;
                }
        }
        buf ^= 1;
    }
#undef FL_LD
#undef FL_ST

    int oy = tileY + threadIdx.y * 2, ox = tileX + threadIdx.x * 2;
#pragma unroll
    for (int o = 0; o < CFL; o++) {
        float bv = flows_b[o];
        float* yp = g_flows + ((size_t)b * CFL + o) * HW;
        yp[oy * WW + ox]           = acc[o][0] + bv;
        yp[oy * WW + ox + 1]       = acc[o][1] + bv;
        yp[(oy + 1) * WW + ox]     = acc[o][2] + bv;
        yp[(oy + 1) * WW + ox + 1] = acc[o][3] + bv;
    }
}

// ==================== bilinear warp -> g_warp ====================
__global__ void warp_kernel(const float* __restrict__ hp)
{
    int idx = blockIdx.x * blockDim.x + threadIdx.x;
    const int total = BB * LL * HW;
    if (idx >= total) return;

    int pix = idx % HW;
    int bl  = idx / HW;
    int l = bl % LL;
    int b = bl / LL;
    int gx = pix % WW;
    int gy = pix / WW;

    const float* fl = g_flows + ((size_t)b * CFL + 2 * l) * HW;
    float fx = fl[pix];
    float fy = fl[HW + pix];

    float vx = (float)gx - fx;
    float vy = (float)gy - fy;
    float gxn = 2.f * vx / (float)(WW - 1) - 1.f;
    float gyn = 2.f * vy / (float)(HH - 1) - 1.f;
    float sx = ((gxn + 1.f) * (float)WW - 1.f) * 0.5f;
    float sy = ((gyn + 1.f) * (float)HH - 1.f) * 0.5f;

    float x0f = floorf(sx), y0f = floorf(sy);
    int x0 = (int)x0f, y0 = (int)y0f;
    int x1 = x0 + 1, y1 = y0 + 1;
    float wx1 = sx - x0f, wx0 = 1.f - wx1;
    float wy1 = sy - y0f, wy0 = 1.f - wy1;

    bool vx0 = (x0 >= 0) && (x0 < WW);
    bool vx1 = (x1 >= 0) && (x1 < WW);
    bool vy0 = (y0 >= 0) && (y0 < HH);
    bool vy1 = (y1 >= 0) && (y1 < HH);

    int xc0 = min(max(x0, 0), WW - 1);
    int xc1 = min(max(x1, 0), WW - 1);
    int yc0 = min(max(y0, 0), HH - 1);
    int yc1 = min(max(y1, 0), HH - 1);

    float w00 = (vy0 && vx0) ? wy0 * wx0 : 0.f;
    float w01 = (vy0 && vx1) ? wy0 * wx1 : 0.f;
    float w10 = (vy1 && vx0) ? wy1 * wx0 : 0.f;
    float w11 = (vy1 && vx1) ? wy1 * wx1 : 0.f;

    int o00 = yc0 * WW + xc0;
    int o01 = yc0 * WW + xc1;
    int o10 = yc1 * WW + xc0;
    int o11 = yc1 * WW + xc1;

    const float* hb = hp + (size_t)b * NF * HW;
    float* ob = g_warp + ((size_t)b * KW + (size_t)l * NF) * HW + pix;

#pragma unroll 8
    for (int c = 0; c < NF; c++) {
        const float* hc = hb + (size_t)c * HW;
        float v = w00 * __ldg(hc + o00) + w01 * __ldg(hc + o01)
                + w10 * __ldg(hc + o10) + w11 * __ldg(hc + o11);
        ob[(size_t)c * HW] = v;
    }
}

// ==================== fused GEMM + gates ====================
// h2h = ret_w @ g_warp + ret_b computed with BM=192 (all gate components in one
// block), then the GRU gate update applied in the epilogue. h2h never hits DRAM.
// BM=192, BN=64, BK=16, 256 threads. Thread (tx,ty): 4 pixels (tx), 4 channels
// (ty) x 3 gate components = 48 accumulators holding aligned (c, c+64, c+128)
// triples. grid (144, BB), block 256.
__global__ void __launch_bounds__(256, 2)
gemm_gates_kernel(const float* __restrict__ Wm, const float* __restrict__ bias,
                  int t, const float* __restrict__ hp, float* __restrict__ hn)
{
    const int K = KW, N = HW;
    __shared__ __align__(16) float Ws[2][16][192];
    __shared__ __align__(16) float As[2][16][64];

    int b  = blockIdx.y;
    int n0 = blockIdx.x * 64;
    int tid = threadIdx.x;
    int tx = tid % 16;        // pixel group: 4 px
    int ty = tid / 16;        // channel group: c0 = ty*4

    const float* Ab = g_warp + (size_t)b * K * N;

    float acc[3][4][4];       // [component][c][px]
#pragma unroll
    for (int g = 0; g < 3; g++)
#pragma unroll
        for (int i = 0; i < 4; i++)
#pragma unroll
            for (int j = 0; j < 4; j++) acc[g][i][j] = 0.f;

    int arow = tid / 16;
    int acol = (tid % 16) * 4;

    float4 pa;
    float pw[12];

#define GG_LD(K0) { \
        pa = *(const float4*)(Ab + (size_t)((K0) + arow) * N + n0 + acol); \
        _Pragma("unroll") \
        for (int r = 0; r < 12; r++) { \
            int i = tid + r * 256; \
            int m = i >> 4, kk = i & 15; \
            pw[r] = Wm[(size_t)m * K + (K0) + kk]; \
        } }
#define GG_ST(BUF) { \
        *(float4*)&As[BUF][arow][acol] = pa; \
        _Pragma("unroll") \
        for (int r = 0; r < 12; r++) { \
            int i = tid + r * 256; \
            int m = i >> 4, kk = i & 15; \
            Ws[BUF][kk][m] = pw[r]; \
        } }

    GG_LD(0);
    int buf = 0;
    for (int k0 = 0; k0 < K; k0 += 16) {
        GG_ST(buf);
        __syncthreads();
        if (k0 + 16 < K) GG_LD(k0 + 16);

#pragma unroll
        for (int kk = 0; kk < 16; kk++) {
            float4 a4 = *(const float4*)&As[buf][kk][tx * 4];
            float4 wr = *(const float4*)&Ws[buf][kk][ty * 4];
            float4 wu = *(const float4*)&Ws[buf][kk][ty * 4 + 64];
            float4 wm = *(const float4*)&Ws[buf][kk][ty * 4 + 128];
#define MM(G, WV) { \
            acc[G][0][0] += WV.x*a4.x; acc[G][0][1] += WV.x*a4.y; acc[G][0][2] += WV.x*a4.z; acc[G][0][3] += WV.x*a4.w; \
            acc[G][1][0] += WV.y*a4.x; acc[G][1][1] += WV.y*a4.y; acc[G][1][2] += WV.y*a4.z; acc[G][1][3] += WV.y*a4.w; \
            acc[G][2][0] += WV.z*a4.x; acc[G][2][1] += WV.z*a4.y; acc[G][2][2] += WV.z*a4.z; acc[G][2][3] += WV.z*a4.w; \
            acc[G][3][0] += WV.w*a4.x; acc[G][3][1] += WV.w*a4.y; acc[G][3][2] += WV.w*a4.z; acc[G][3][3] += WV.w*a4.w; }
            MM(0, wr) MM(1, wu) MM(2, wm)
#undef MM
        }
        buf ^= 1;
    }
#undef GG_LD
#undef GG_ST

    // epilogue: GRU gates for this thread's 4 channels x 4 pixels
    const float* i2h_t = g_i2h + (size_t)t * BB * C3 * HW;
    int np = n0 + tx * 4;

#pragma unroll
    for (int i = 0; i < 4; i++) {
        int c = ty * 4 + i;
        size_t base = ((size_t)b * C3 + c) * HW + np;
        float4 ir = *(const float4*)&i2h_t[base];
        float4 iu = *(const float4*)&i2h_t[base + (size_t)NF * HW];
        float4 im = *(const float4*)&i2h_t[base + (size_t)2 * NF * HW];
        float4 hp4 = *(const float4*)&hp[((size_t)b * NF + c) * HW + np];
        float br = bias[c], bu = bias[c + NF], bm = bias[c + 2 * NF];

        float4 outv;
#define GATE1(X, J) { \
        float r = fsigmoid(ir.X + acc[0][i][J] + br); \
        float u = fsigmoid(iu.X + acc[1][i][J] + bu); \
        float m = ftanh(im.X + r * (acc[2][i][J] + bm)); \
        outv.X = u * hp4.X + (1.f - u) * m; }
        GATE1(x, 0) GATE1(y, 1) GATE1(z, 2) GATE1(w, 3)
#undef GATE1

        *(float4*)&hn[((size_t)b * NF + c) * HW + np] = outv;
    }
}

// ==================== gates for t=0 only (h_prev = 0, h2h = bias) ====================
__global__ void gates_first_kernel(float* __restrict__ hn, const float* __restrict__ ret_b)
{
    int idx = blockIdx.x * blockDim.x + threadIdx.x;
    const int total4 = BB * NF * HW / 4;
    if (idx >= total4) return;

    int e = idx * 4;
    int pix = e % HW;
    int rest = e / HW;
    int c = rest % NF;
    int b = rest / NF;

    const float* i2h_t = g_i2h;   // t = 0
    size_t base = ((size_t)b * C3 + c) * HW + pix;
    float4 ir = *(const float4*)&i2h_t[base];
    float4 iu = *(const float4*)&i2h_t[base + (size_t)NF * HW];
    float4 im = *(const float4*)&i2h_t[base + (size_t)2 * NF * HW];

    float br = ret_b[c], bu = ret_b[c + NF], bm = ret_b[c + 2 * NF];

    float4 outv;
#define GATE1(X) { \
        float r = fsigmoid(ir.X + br); \
        float u = fsigmoid(iu.X + bu); \
        float m = ftanh(im.X + r * bm); \
        outv.X = (1.f - u) * m; }
    GATE1(x) GATE1(y) GATE1(z) GATE1(w)
#undef GATE1

    *(float4*)&hn[((size_t)b * NF + c) * HW + pix] = outv;
}

// -------------------- launcher --------------------
extern "C" void kernel_launch(void* const* d_in, const int* in_sizes, int n_in,
                              void* d_out, int out_size)
{
    const float* inputs  = (const float*)d_in[0];
    const float* i2h_w   = (const float*)d_in[1];
    const float* i2h_b   = (const float*)d_in[2];
    const float* i2f_w   = (const float*)d_in[3];
    const float* i2f_b   = (const float*)d_in[4];
    const float* h2f_w   = (const float*)d_in[5];
    const float* h2f_b   = (const float*)d_in[6];
    const float* flows_w = (const float*)d_in[7];
    const float* flows_b = (const float*)d_in[8];
    const float* ret_w   = (const float*)d_in[9];
    const float* ret_b   = (const float*)d_in[10];
    float* out = (float*)d_out;

    const int hstride = BB * NF * HW;
    const dim3 thr16(16, 16);

    conv3_kernel<<<dim3(9, C3 / 16, SEQ * BB), thr16>>>(inputs, i2h_w, i2h_b);

    for (int t = 0; t < SEQ; t++) {
        const float* x_t   = inputs + (size_t)t * BB * CIN * HW;
        const float* hprev = (t == 0) ? nullptr : out + (size_t)(t - 1) * hstride;
        float* hnew        = out + (size_t)t * hstride;
        int first = (t == 0) ? 1 : 0;

        conv5_f_kernel<<<dim3(9, CF / 8, BB), thr16>>>(x_t, hprev, i2f_w, h2f_w,
                                                       i2f_b, h2f_b, first);

        if (first) {
            gates_first_kernel<<<(hstride / 4 + 255) / 256, 256>>>(hnew, ret_b);
        } else {
            conv5_flows_kernel<<<dim3(9, 1, BB), thr16>>>(flows_w, flows_b);
            warp_kernel<<<(BB * LL * HW + 255) / 256, 256>>>(hprev);
            gemm_gates_kernel<<<dim3(HW / 64, BB), 256>>>(ret_w, ret_b, t, hprev, hnew);
        }
    }

    if (out_size >= (SEQ + 1) * hstride) {
        copy_kernel<<<(hstride + 255) / 256, 256>>>(out + (size_t)(SEQ - 1) * hstride,
                                                    out + (size_t)SEQ * hstride, hstride);
    }
}